// round 1
// baseline (speedup 1.0000x reference)
#include <cuda_runtime.h>

#define NB   256      // batches
#define NQ   1000     // queries
#define NC   80       // classes
#define QC   80000    // NQ*NC
#define K    300      // top-k
#define NBINS 4096
#define CAP   4096
#define NTH   512

// order-preserving float -> uint key (larger key == larger float)
__device__ __forceinline__ unsigned key_of(float x) {
    unsigned u = __float_as_uint(x);
    return (u & 0x80000000u) ? ~u : (u | 0x80000000u);
}
__device__ __forceinline__ float val_of(unsigned k) {
    unsigned u = (k & 0x80000000u) ? (k ^ 0x80000000u) : ~k;
    return __uint_as_float(u);
}

__global__ __launch_bounds__(NTH)
void rtdetr_topk_kernel(const float* __restrict__ logits,
                        const float* __restrict__ boxes,
                        const float* __restrict__ sizes,
                        float* __restrict__ out)
{
    __shared__ union {
        unsigned hist[NBINS];
        unsigned long long cand[CAP];
    } sm;
    __shared__ unsigned scan[NTH];
    __shared__ unsigned s_bin;
    __shared__ unsigned s_cnt;

    const int b   = blockIdx.x;
    const int tid = threadIdx.x;
    const float4* base = (const float4*)(logits + (size_t)b * QC);
    const int NV = QC / 4;   // 20000 float4 per batch

    // ---- zero histogram ----
    #pragma unroll
    for (int i = tid; i < NBINS; i += NTH) sm.hist[i] = 0;
    if (tid == 0) s_cnt = 0;
    __syncthreads();

    // ---- pass 1: 12-bit histogram of keys ----
    for (int i = tid; i < NV; i += NTH) {
        float4 v = base[i];
        atomicAdd(&sm.hist[key_of(v.x) >> 20], 1u);
        atomicAdd(&sm.hist[key_of(v.y) >> 20], 1u);
        atomicAdd(&sm.hist[key_of(v.z) >> 20], 1u);
        atomicAdd(&sm.hist[key_of(v.w) >> 20], 1u);
    }
    __syncthreads();

    // ---- per-thread chunk sums (8 bins each), then suffix scan ----
    unsigned csum = 0;
    #pragma unroll
    for (int j = 0; j < 8; j++) csum += sm.hist[tid * 8 + j];
    scan[tid] = csum;
    __syncthreads();
    for (int d = 1; d < NTH; d <<= 1) {
        unsigned add = (tid + d < NTH) ? scan[tid + d] : 0u;
        __syncthreads();
        scan[tid] += add;
        __syncthreads();
    }
    // scan[t] = count of elements whose bin >= t*8

    // ---- find threshold bin b*: smallest bin with count(bin >= b*) >= K ----
    {
        unsigned here  = scan[tid];
        unsigned above = (tid + 1 < NTH) ? scan[tid + 1] : 0u;
        if (here >= K && above < K) {
            unsigned run = above;
            #pragma unroll
            for (int j = 7; j >= 0; j--) {
                run += sm.hist[tid * 8 + j];
                if (run >= K) { s_bin = (unsigned)(tid * 8 + j); break; }
            }
        }
    }
    __syncthreads();
    const unsigned bsel = s_bin;
    __syncthreads();   // done reading hist; cand aliases it

    // ---- pass 2: compact candidates (key >> 20 >= bsel) ----
    for (int i = tid; i < NV; i += NTH) {
        float4 v = base[i];
        unsigned kk[4];
        kk[0] = key_of(v.x); kk[1] = key_of(v.y);
        kk[2] = key_of(v.z); kk[3] = key_of(v.w);
        #pragma unroll
        for (int j = 0; j < 4; j++) {
            if ((kk[j] >> 20) >= bsel) {
                unsigned p = atomicAdd(&s_cnt, 1u);
                if (p < CAP) {
                    unsigned idx = (unsigned)(4 * i + j);
                    sm.cand[p] = ((unsigned long long)kk[j] << 32)
                               | (unsigned long long)(~idx);
                }
            }
        }
    }
    __syncthreads();

    unsigned M = min(s_cnt, (unsigned)CAP);
    unsigned n = 1;
    while (n < M) n <<= 1;          // next pow2, <= 4096
    for (unsigned i = M + tid; i < n; i += NTH) sm.cand[i] = 0ull;
    __syncthreads();

    // ---- bitonic sort descending (composite = key<<32 | ~idx) ----
    for (unsigned kk = 2; kk <= n; kk <<= 1) {
        for (unsigned j = kk >> 1; j > 0; j >>= 1) {
            for (unsigned i = tid; i < n; i += NTH) {
                unsigned l = i ^ j;
                if (l > i) {
                    unsigned long long a = sm.cand[i];
                    unsigned long long c = sm.cand[l];
                    bool desc = ((i & kk) == 0);
                    if (desc ? (a < c) : (a > c)) {
                        sm.cand[i] = c; sm.cand[l] = a;
                    }
                }
            }
            __syncthreads();
        }
    }

    // ---- epilogue: top K -> labels, boxes, scores ----
    if (tid < K) {
        unsigned long long comp = sm.cand[tid];
        unsigned kk  = (unsigned)(comp >> 32);
        unsigned idx = ~(unsigned)comp;
        float x = val_of(kk);
        float score = 1.0f / (1.0f + expf(-x));
        int label = (int)(idx % NC);
        int q     = (int)(idx / NC);

        float4 bx = ((const float4*)(boxes + ((size_t)b * NQ + q) * 4))[0];
        float w = sizes[2 * b], h = sizes[2 * b + 1];
        float hw = 0.5f * bx.z, hh = 0.5f * bx.w;

        int o = b * K + tid;
        out[o] = (float)label;                     // labels [B,K]
        float* ob = out + NB * K + (size_t)o * 4;  // boxes  [B,K,4]
        ob[0] = (bx.x - hw) * w;
        ob[1] = (bx.y - hh) * h;
        ob[2] = (bx.x + hw) * w;
        ob[3] = (bx.y + hh) * h;
        out[(size_t)NB * K * 5 + o] = score;       // scores [B,K]
    }
}

extern "C" void kernel_launch(void* const* d_in, const int* in_sizes, int n_in,
                              void* d_out, int out_size) {
    const float* logits = (const float*)d_in[0];
    const float* boxes  = (const float*)d_in[1];
    const float* sizes  = (const float*)d_in[2];
    float* out = (float*)d_out;
    rtdetr_topk_kernel<<<NB, NTH>>>(logits, boxes, sizes, out);
}